// round 7
// baseline (speedup 1.0000x reference)
#include <cuda_runtime.h>
#include <cstdint>
#include <math.h>

#define B_  128
#define T_  256
#define D_  256
#define U_  256
#define NG  768
#define M_  (B_ * T_)

__device__ float g_xz[M_ * NG];        // x@kernel + bias
__device__ float g_subo[3 * B_ * T_];  // sub_out[s][b][t]
__device__ float g_hbuf[2][B_ * U_];   // h double buffer

// ---------------------------------------------------------------- init
__global__ void k0_init() {
    int i = blockIdx.x * blockDim.x + threadIdx.x;
    if (i < B_ * U_) g_hbuf[0][i] = 0.f;
}

// ---------------------------------------------------------------- k1: GEMM
__global__ __launch_bounds__(256) void k1_gemm(const float* __restrict__ x,
                                               const float* __restrict__ w,
                                               const float* __restrict__ bias) {
    __shared__ float As[8][132];
    __shared__ float Bs[8][128];
    const int tid = threadIdx.x;
    const int n0 = blockIdx.x * 128, m0 = blockIdx.y * 128;
    const int tm = (tid >> 4) * 8, tn = (tid & 15) * 8;
    const int mA = tid >> 1, kq = (tid & 1) * 4;
    const int rB = tid >> 5, cB = (tid & 31) * 4;

    float acc[8][8];
#pragma unroll
    for (int i = 0; i < 8; i++)
#pragma unroll
        for (int j = 0; j < 8; j++) acc[i][j] = 0.f;

    for (int k0 = 0; k0 < 256; k0 += 8) {
        __syncthreads();
        float4 av = *reinterpret_cast<const float4*>(&x[(m0 + mA) * 256 + k0 + kq]);
        As[kq + 0][mA] = av.x; As[kq + 1][mA] = av.y;
        As[kq + 2][mA] = av.z; As[kq + 3][mA] = av.w;
        *reinterpret_cast<float4*>(&Bs[rB][cB]) =
            *reinterpret_cast<const float4*>(&w[(k0 + rB) * NG + n0 + cB]);
        __syncthreads();
#pragma unroll
        for (int k = 0; k < 8; k++) {
            float a[8], b[8];
            *reinterpret_cast<float4*>(a)     = *reinterpret_cast<float4*>(&As[k][tm]);
            *reinterpret_cast<float4*>(a + 4) = *reinterpret_cast<float4*>(&As[k][tm + 4]);
            *reinterpret_cast<float4*>(b)     = *reinterpret_cast<float4*>(&Bs[k][tn]);
            *reinterpret_cast<float4*>(b + 4) = *reinterpret_cast<float4*>(&Bs[k][tn + 4]);
#pragma unroll
            for (int i = 0; i < 8; i++)
#pragma unroll
                for (int j = 0; j < 8; j++) acc[i][j] += a[i] * b[j];
        }
    }
    float bi[8];
    *reinterpret_cast<float4*>(bi)     = *reinterpret_cast<const float4*>(&bias[n0 + tn]);
    *reinterpret_cast<float4*>(bi + 4) = *reinterpret_cast<const float4*>(&bias[n0 + tn + 4]);
#pragma unroll
    for (int i = 0; i < 8; i++) {
        float* dst = &g_xz[(m0 + tm + i) * NG + n0 + tn];
#pragma unroll
        for (int j = 0; j < 8; j++) dst[j] = acc[i][j] + bi[j];
    }
}

// ---------------------------------------------------------------- k2: sub-TKAN/KAN
__global__ __launch_bounds__(256) void k2_sub(const float* __restrict__ x,
                                              const float* __restrict__ stk,   // (3,2)
                                              const float* __restrict__ srk,   // (3,512)
                                              const float* __restrict__ kbw,   // (3,256,1)
                                              const float* __restrict__ ksw) { // (3,256,8,1)
    __shared__ float sw[256 * 9];
    __shared__ float wpart[8];
    __shared__ float bcast;
    const int s = blockIdx.x >> 7, b = blockIdx.x & 127;
    const int d = threadIdx.x, lane = d & 31, wid = d >> 5;

    const float skx = srk[s * 512 + d];
    const float skh = srk[s * 512 + 256 + d];
    const float bw  = kbw[s * 256 + d];
    const float rh  = stk[s * 2 + 0];
    const float rx  = stk[s * 2 + 1];
#pragma unroll
    for (int c = 0; c < 8; c++) sw[d * 9 + c] = ksw[(s * 256 + d) * 8 + c];
    __syncthreads();

    float sub = 0.f;
    const float* xp = x + (b * T_) * D_ + d;
    float* so = g_subo + (s * B_ + b) * T_;

    for (int t = 0; t < T_; t++) {
        const float v = xp[t * D_] * skx + sub * skh;
        float e = (v / (1.f + expf(-v))) * bw;                 // silu * base_w
        const float xg = (v + 2.2f) * 2.5f;
        const float fj = floorf(xg);
        const int j = (int)fj;
        if (j >= 0 && j <= 10) {
            const float wl = xg - fj, w2 = wl * wl, w3 = w2 * wl;
            const float omw = 1.f - wl;
            const float n0 = (1.f / 6.f) * omw * omw * omw;
            const float n1 = (1.f / 6.f) * (3.f * w3 - 6.f * w2 + 4.f);
            const float n2 = (1.f / 6.f) * (-3.f * w3 + 3.f * w2 + 3.f * wl + 1.f);
            const float n3 = (1.f / 6.f) * w3;
            const int c0 = j - 3;
            const float* swd = &sw[d * 9];
            if (c0     >= 0 && c0     < 8) e += n0 * swd[c0];
            if (c0 + 1 >= 0 && c0 + 1 < 8) e += n1 * swd[c0 + 1];
            if (c0 + 2 >= 0 && c0 + 2 < 8) e += n2 * swd[c0 + 2];
            if (c0 + 3 >= 0 && c0 + 3 < 8) e += n3 * swd[c0 + 3];
        }
#pragma unroll
        for (int off = 16; off > 0; off >>= 1) e += __shfl_xor_sync(0xffffffffu, e, off);
        if (lane == 0) wpart[wid] = e;
        __syncthreads();
        if (d == 0) {
            float tot = 0.f;
#pragma unroll
            for (int ww = 0; ww < 8; ww++) tot += wpart[ww];
            so[t] = tot;
            bcast = rh * tot + rx * sub;
        }
        __syncthreads();
        sub = bcast;
    }
}

// ---------------------------------------------------------------- k3: recurrence
// grid 128, cluster 8. CTA: btile = bx>>3 (8 batches), utile = bx&7 (32 u's).
// thread compute role: kg = tid>>5 (k-range 32), u' = tid&31 (weights in regs).
// thread gate role: b = tid>>5, u' = tid&31 (owns c state).
__global__ __launch_bounds__(256) __cluster_dims__(8, 1, 1)
void k3_rnn(const float* __restrict__ rk,   // (256,768)
            const float* __restrict__ aw,   // (3,256)
            const float* __restrict__ ab,   // (256)
            float* __restrict__ out) {      // (B,T,U)
    __shared__ float hs[8 * 256];
    __shared__ float red[8 * 32 * 27];
    const int tid = threadIdx.x;
    const int wid = tid >> 5, lane = tid & 31;
    const int u0 = (blockIdx.x & 7) * 32;
    const int b0 = (blockIdx.x >> 3) * 8;
    const int k0 = wid * 32;

    // recurrent weights -> registers (loaded once)
    float wi[32], wf[32], wc[32];
#pragma unroll
    for (int kk = 0; kk < 32; kk++) {
        const int kr = (k0 + kk) * NG + u0 + lane;
        wi[kk] = rk[kr]; wf[kk] = rk[kr + 256]; wc[kk] = rk[kr + 512];
    }
    // gate-role constants
    const int gb = b0 + wid;                 // global batch for gate role
    const int gu = u0 + lane;                // global u
    const float aw0 = aw[gu], aw1 = aw[256 + gu], aw2 = aw[512 + gu];
    const float abr = ab[gu];
    const float* so0 = g_subo + (0 * B_ + gb) * T_;
    const float* so1 = g_subo + (1 * B_ + gb) * T_;
    const float* so2 = g_subo + (2 * B_ + gb) * T_;
    const float* xzp = g_xz + (size_t)(gb * T_) * NG + gu;
    float* yp = out + (size_t)(gb * T_) * U_ + gu;
    float c = 0.f;

    for (int t = 0; t < T_; t++) {
        // stage h (8 batches x 256) into smem
        const float4* src = reinterpret_cast<const float4*>(&g_hbuf[t & 1][b0 * 256]);
        float4* dst = reinterpret_cast<float4*>(hs);
        dst[tid * 2]     = __ldcg(&src[tid * 2]);
        dst[tid * 2 + 1] = __ldcg(&src[tid * 2 + 1]);
        // early loads for gate phase (independent of hs)
        const float xz0 = __ldg(&xzp[(size_t)t * NG]);
        const float xz1 = __ldg(&xzp[(size_t)t * NG + 256]);
        const float xz2 = __ldg(&xzp[(size_t)t * NG + 512]);
        const float s0 = __ldg(&so0[t]), s1 = __ldg(&so1[t]), s2 = __ldg(&so2[t]);
        __syncthreads();

        // compute partial dot products: all h loads are warp-uniform broadcasts
        float ai[8], af8[8], ac8[8];
#pragma unroll
        for (int b = 0; b < 8; b++) { ai[b] = 0.f; af8[b] = 0.f; ac8[b] = 0.f; }
#pragma unroll
        for (int b = 0; b < 8; b++) {
            const float4* h4p = reinterpret_cast<const float4*>(&hs[b * 256 + k0]);
#pragma unroll
            for (int q = 0; q < 8; q++) {
                const float4 h4 = h4p[q];
                const int kb = q * 4;
                ai[b]  += h4.x * wi[kb] + h4.y * wi[kb + 1] + h4.z * wi[kb + 2] + h4.w * wi[kb + 3];
                af8[b] += h4.x * wf[kb] + h4.y * wf[kb + 1] + h4.z * wf[kb + 2] + h4.w * wf[kb + 3];
                ac8[b] += h4.x * wc[kb] + h4.y * wc[kb + 1] + h4.z * wc[kb + 2] + h4.w * wc[kb + 3];
            }
        }
        // write partials: stride 27 over lanes -> conflict free
#pragma unroll
        for (int b = 0; b < 8; b++) {
            const int base = (b * 32 + lane) * 27 + wid;
            red[base] = ai[b]; red[base + 9] = af8[b]; red[base + 18] = ac8[b];
        }
        __syncthreads();

        // gate phase: thread = (b=wid, u'=lane)
        float zi = xz0, zf = xz1, zc = xz2;
        const int rbase = (wid * 32 + lane) * 27;
#pragma unroll
        for (int kg = 0; kg < 8; kg++) {
            zi += red[rbase + kg];
            zf += red[rbase + 9 + kg];
            zc += red[rbase + 18 + kg];
        }
        const float ig = 1.f / (1.f + expf(-zi));
        const float fg = 1.f / (1.f + expf(-zf));
        c = fg * c + ig * tanhf(zc);
        const float oarg = s0 * aw0 + s1 * aw1 + s2 * aw2 + abr;
        const float o = 1.f / (1.f + expf(-oarg));
        const float h = o * tanhf(c);
        __stcg(&g_hbuf[(t + 1) & 1][gb * 256 + gu], h);
        yp[(size_t)t * U_] = h;

        __threadfence();
        asm volatile("barrier.cluster.arrive.aligned;\n\t"
                     "barrier.cluster.wait.aligned;" ::: "memory");
    }
}

// ---------------------------------------------------------------- launch
extern "C" void kernel_launch(void* const* d_in, const int* in_sizes, int n_in,
                              void* d_out, int out_size) {
    const float* x    = (const float*)d_in[0];
    const float* ker  = (const float*)d_in[1];
    const float* rk   = (const float*)d_in[2];
    const float* bias = (const float*)d_in[3];
    const float* stk  = (const float*)d_in[4];
    const float* srk  = (const float*)d_in[5];
    const float* aw   = (const float*)d_in[6];
    const float* ab   = (const float*)d_in[7];
    const float* kbw  = (const float*)d_in[8];
    const float* ksw  = (const float*)d_in[9];
    float* out = (float*)d_out;

    k0_init<<<(B_ * U_ + 255) / 256, 256>>>();
    k1_gemm<<<dim3(NG / 128, M_ / 128), 256>>>(x, ker, bias);
    k2_sub<<<3 * B_, 256>>>(x, stk, srk, kbw, ksw);
    k3_rnn<<<128, 256>>>(rk, aw, ab, out);
}

// round 8
// speedup vs baseline: 1.0593x; 1.0593x over previous
#include <cuda_runtime.h>
#include <cstdint>
#include <math.h>

#define B_  128
#define T_  256
#define D_  256
#define U_  256
#define NG  768
#define M_  (B_ * T_)

typedef unsigned long long u64;

__device__ float g_xz[M_ * NG];        // x@kernel + bias
__device__ float g_subo[3 * B_ * T_];  // sub_out[s][b][t]

// ---------------- f32x2 helpers (FFMA2 only reachable via PTX) ------------
__device__ __forceinline__ u64 pack2(float lo, float hi) {
    u64 r;
    asm("mov.b64 %0, {%1, %2};" : "=l"(r)
        : "r"(__float_as_uint(lo)), "r"(__float_as_uint(hi)));
    return r;
}
__device__ __forceinline__ u64 fma2(u64 a, u64 b, u64 c) {
    u64 d;
    asm("fma.rn.f32x2 %0, %1, %2, %3;" : "=l"(d) : "l"(a), "l"(b), "l"(c));
    return d;
}
__device__ __forceinline__ float2 unpack2(u64 v) {
    uint32_t lo, hi;
    asm("mov.b64 {%0, %1}, %2;" : "=r"(lo), "=r"(hi) : "l"(v));
    return make_float2(__uint_as_float(lo), __uint_as_float(hi));
}
__device__ __forceinline__ uint32_t smem_u32(const void* p) {
    uint32_t a;
    asm("{ .reg .u64 t; cvta.to.shared.u64 t, %1; cvt.u32.u64 %0, t; }"
        : "=r"(a) : "l"(p));
    return a;
}
__device__ __forceinline__ void st_cluster_f32(uint32_t laddr, int rank, float v) {
    uint32_t raddr;
    asm volatile("mapa.shared::cluster.u32 %0, %1, %2;"
                 : "=r"(raddr) : "r"(laddr), "r"(rank));
    asm volatile("st.shared::cluster.f32 [%0], %1;" :: "r"(raddr), "f"(v) : "memory");
}

// ---------------------------------------------------------------- k1: GEMM (f32x2)
__global__ __launch_bounds__(256, 2) void k1_gemm(const float* __restrict__ x,
                                                  const float* __restrict__ w,
                                                  const float* __restrict__ bias) {
    __shared__ __align__(16) float As[8][132];   // 132*4 = 528 = 33*16 -> rows 16B aligned
    __shared__ __align__(16) float Bs[8][128];
    const int tid = threadIdx.x;
    const int n0 = blockIdx.x * 128, m0 = blockIdx.y * 128;
    const int tm = (tid >> 4) * 8, tn = (tid & 15) * 8;
    const int mA = tid >> 1, kq = (tid & 1) * 4;
    const int rB = tid >> 5, cB = (tid & 31) * 4;

    u64 acc2[4][8];   // pairs along m: acc2[p][j] = (acc[2p][j], acc[2p+1][j])
#pragma unroll
    for (int p = 0; p < 4; p++)
#pragma unroll
        for (int j = 0; j < 8; j++) acc2[p][j] = 0ull;

    for (int k0 = 0; k0 < 256; k0 += 8) {
        __syncthreads();
        float4 av = *reinterpret_cast<const float4*>(&x[(m0 + mA) * 256 + k0 + kq]);
        As[kq + 0][mA] = av.x; As[kq + 1][mA] = av.y;
        As[kq + 2][mA] = av.z; As[kq + 3][mA] = av.w;
        *reinterpret_cast<float4*>(&Bs[rB][cB]) =
            *reinterpret_cast<const float4*>(&w[(k0 + rB) * NG + n0 + cB]);
        __syncthreads();
#pragma unroll
        for (int k = 0; k < 8; k++) {
            const ulonglong2* ap = reinterpret_cast<const ulonglong2*>(&As[k][tm]);
            const ulonglong2 aA = ap[0], aB = ap[1];
            const u64 a2[4] = {aA.x, aA.y, aB.x, aB.y};
            float b[8];
            *reinterpret_cast<float4*>(b)     = *reinterpret_cast<float4*>(&Bs[k][tn]);
            *reinterpret_cast<float4*>(b + 4) = *reinterpret_cast<float4*>(&Bs[k][tn + 4]);
            u64 b2[8];
#pragma unroll
            for (int j = 0; j < 8; j++) b2[j] = pack2(b[j], b[j]);
#pragma unroll
            for (int p = 0; p < 4; p++)
#pragma unroll
                for (int j = 0; j < 8; j++) acc2[p][j] = fma2(a2[p], b2[j], acc2[p][j]);
        }
    }
    float bi[8];
    *reinterpret_cast<float4*>(bi)     = *reinterpret_cast<const float4*>(&bias[n0 + tn]);
    *reinterpret_cast<float4*>(bi + 4) = *reinterpret_cast<const float4*>(&bias[n0 + tn + 4]);
#pragma unroll
    for (int p = 0; p < 4; p++) {
        float r0[8], r1[8];
#pragma unroll
        for (int j = 0; j < 8; j++) {
            float2 v = unpack2(acc2[p][j]);
            r0[j] = v.x + bi[j];
            r1[j] = v.y + bi[j];
        }
        float* d0 = &g_xz[(size_t)(m0 + tm + 2 * p) * NG + n0 + tn];
        float* d1 = d0 + NG;
#pragma unroll
        for (int j = 0; j < 8; j++) { d0[j] = r0[j]; d1[j] = r1[j]; }
    }
}

// ---------------------------------------------------------------- k2: sub-TKAN/KAN
__global__ __launch_bounds__(256) void k2_sub(const float* __restrict__ x,
                                              const float* __restrict__ stk,   // (3,2)
                                              const float* __restrict__ srk,   // (3,512)
                                              const float* __restrict__ kbw,   // (3,256,1)
                                              const float* __restrict__ ksw) { // (3,256,8,1)
    __shared__ float sw[256 * 9];
    __shared__ float wpart[8];
    __shared__ float bcast;
    const int s = blockIdx.x >> 7, b = blockIdx.x & 127;
    const int d = threadIdx.x, lane = d & 31, wid = d >> 5;

    const float skx = srk[s * 512 + d];
    const float skh = srk[s * 512 + 256 + d];
    const float bw  = kbw[s * 256 + d];
    const float rh  = stk[s * 2 + 0];
    const float rx  = stk[s * 2 + 1];
#pragma unroll
    for (int c = 0; c < 8; c++) sw[d * 9 + c] = ksw[(s * 256 + d) * 8 + c];
    __syncthreads();

    float sub = 0.f;
    const float* xp = x + (b * T_) * D_ + d;
    float* so = g_subo + (s * B_ + b) * T_;

    for (int t = 0; t < T_; t++) {
        const float v = xp[t * D_] * skx + sub * skh;
        float e = (v / (1.f + expf(-v))) * bw;
        const float xg = (v + 2.2f) * 2.5f;
        const float fj = floorf(xg);
        const int j = (int)fj;
        if (j >= 0 && j <= 10) {
            const float wl = xg - fj, w2 = wl * wl, w3 = w2 * wl;
            const float omw = 1.f - wl;
            const float n0 = (1.f / 6.f) * omw * omw * omw;
            const float n1 = (1.f / 6.f) * (3.f * w3 - 6.f * w2 + 4.f);
            const float n2 = (1.f / 6.f) * (-3.f * w3 + 3.f * w2 + 3.f * wl + 1.f);
            const float n3 = (1.f / 6.f) * w3;
            const int c0 = j - 3;
            const float* swd = &sw[d * 9];
            if (c0     >= 0 && c0     < 8) e += n0 * swd[c0];
            if (c0 + 1 >= 0 && c0 + 1 < 8) e += n1 * swd[c0 + 1];
            if (c0 + 2 >= 0 && c0 + 2 < 8) e += n2 * swd[c0 + 2];
            if (c0 + 3 >= 0 && c0 + 3 < 8) e += n3 * swd[c0 + 3];
        }
#pragma unroll
        for (int off = 16; off > 0; off >>= 1) e += __shfl_xor_sync(0xffffffffu, e, off);
        if (lane == 0) wpart[wid] = e;
        __syncthreads();
        if (d == 0) {
            float tot = 0.f;
#pragma unroll
            for (int ww = 0; ww < 8; ww++) tot += wpart[ww];
            so[t] = tot;
            bcast = rh * tot + rx * sub;
        }
        __syncthreads();
        sub = bcast;
    }
}

// ---------------------------------------------------------------- k3: recurrence
// grid 128, cluster 8 (cluster = one btile of 8 batches; rank = utile).
// h exchange is DSMEM-only: after gate phase each thread broadcasts its h to
// all 8 cluster CTAs' smem; cluster barrier gives release/acquire ordering.
__global__ __launch_bounds__(256, 1) __cluster_dims__(8, 1, 1)
void k3_rnn(const float* __restrict__ rk,   // (256,768)
            const float* __restrict__ aw,   // (3,256)
            const float* __restrict__ ab,   // (256)
            float* __restrict__ out) {      // (B,T,U)
    __shared__ __align__(16) float hs[2][2048];   // [buf][b_local*256 + u]
    __shared__ float red[8 * 32 * 27];
    const int tid = threadIdx.x;
    const int wid = tid >> 5, lane = tid & 31;
    const int u0 = (blockIdx.x & 7) * 32;
    const int b0 = (blockIdx.x >> 3) * 8;
    const int k0 = wid * 32;

    // recurrent weights packed along k into registers (once)
    u64 wi2[16], wf2[16], wc2[16];
#pragma unroll
    for (int kk = 0; kk < 16; kk++) {
        const int r0 = (k0 + 2 * kk) * NG + u0 + lane;
        const int r1 = r0 + NG;
        wi2[kk] = pack2(rk[r0],       rk[r1]);
        wf2[kk] = pack2(rk[r0 + 256], rk[r1 + 256]);
        wc2[kk] = pack2(rk[r0 + 512], rk[r1 + 512]);
    }
    // gate-role constants: thread owns cell (b = b0+wid, u = u0+lane)
    const int gb = b0 + wid;
    const int gu = u0 + lane;
    const float aw0 = aw[gu], aw1 = aw[256 + gu], aw2 = aw[512 + gu];
    const float abr = ab[gu];
    const float* so0 = g_subo + (0 * B_ + gb) * T_;
    const float* so1 = g_subo + (1 * B_ + gb) * T_;
    const float* so2 = g_subo + (2 * B_ + gb) * T_;
    const float* xzp = g_xz + (size_t)(gb * T_) * NG + gu;
    float* yp = out + (size_t)(gb * T_) * U_ + gu;
    const uint32_t hw_addr0 = smem_u32(&hs[0][wid * 256 + u0 + lane]);
    const uint32_t hw_addr1 = smem_u32(&hs[1][wid * 256 + u0 + lane]);

    // init h(0) = 0 locally, then cluster-sync
    for (int i = tid; i < 2048; i += 256) hs[0][i] = 0.f;
    asm volatile("barrier.cluster.arrive.aligned;\n\t"
                 "barrier.cluster.wait.aligned;" ::: "memory");

    float c = 0.f;
    for (int t = 0; t < T_; t++) {
        const int p = t & 1;
        // prefetch gate inputs (independent of hs)
        const float xz0 = __ldg(&xzp[(size_t)t * NG]);
        const float xz1 = __ldg(&xzp[(size_t)t * NG + 256]);
        const float xz2 = __ldg(&xzp[(size_t)t * NG + 512]);
        const float s0 = __ldg(&so0[t]), s1 = __ldg(&so1[t]), s2 = __ldg(&so2[t]);

        // compute role: (kg = wid, u' = lane); f32x2 FMA, h pairs straight
        // from LDS.128 halves (all lanes broadcast the same address)
#pragma unroll
        for (int b = 0; b < 8; b++) {
            u64 ai = 0ull, af = 0ull, ac = 0ull;
            const ulonglong2* hp =
                reinterpret_cast<const ulonglong2*>(&hs[p][b * 256 + k0]);
#pragma unroll
            for (int q = 0; q < 8; q++) {
                const ulonglong2 hq = hp[q];
                ai = fma2(hq.x, wi2[2 * q], ai); ai = fma2(hq.y, wi2[2 * q + 1], ai);
                af = fma2(hq.x, wf2[2 * q], af); af = fma2(hq.y, wf2[2 * q + 1], af);
                ac = fma2(hq.x, wc2[2 * q], ac); ac = fma2(hq.y, wc2[2 * q + 1], ac);
            }
            const float2 vi = unpack2(ai), vf = unpack2(af), vc = unpack2(ac);
            const int base = (b * 32 + lane) * 27 + wid;   // stride 27: conflict-free
            red[base]      = vi.x + vi.y;
            red[base + 9]  = vf.x + vf.y;
            red[base + 18] = vc.x + vc.y;
        }
        __syncthreads();

        // gate role: (b = wid, u' = lane)
        float zi = xz0, zf = xz1, zc = xz2;
        const int rbase = (wid * 32 + lane) * 27;
#pragma unroll
        for (int kg = 0; kg < 8; kg++) {
            zi += red[rbase + kg];
            zf += red[rbase + 9 + kg];
            zc += red[rbase + 18 + kg];
        }
        const float ig = 1.f / (1.f + expf(-zi));
        const float fg = 1.f / (1.f + expf(-zf));
        c = fg * c + ig * tanhf(zc);
        const float oarg = s0 * aw0 + s1 * aw1 + s2 * aw2 + abr;
        const float o = 1.f / (1.f + expf(-oarg));
        const float h = o * tanhf(c);

        // DSMEM broadcast h into next buffer of every cluster CTA
        const uint32_t laddr = p ? hw_addr0 : hw_addr1;
#pragma unroll
        for (int r = 0; r < 8; r++) st_cluster_f32(laddr, r, h);

        yp[(size_t)t * U_] = h;

        // cluster barrier: release my DSMEM stores, acquire peers' (also acts
        // as the CTA-wide sync separating red reads from next step's writes)
        asm volatile("barrier.cluster.arrive.aligned;\n\t"
                     "barrier.cluster.wait.aligned;" ::: "memory");
    }
}

// ---------------------------------------------------------------- launch
extern "C" void kernel_launch(void* const* d_in, const int* in_sizes, int n_in,
                              void* d_out, int out_size) {
    const float* x    = (const float*)d_in[0];
    const float* ker  = (const float*)d_in[1];
    const float* rk   = (const float*)d_in[2];
    const float* bias = (const float*)d_in[3];
    const float* stk  = (const float*)d_in[4];
    const float* srk  = (const float*)d_in[5];
    const float* aw   = (const float*)d_in[6];
    const float* ab   = (const float*)d_in[7];
    const float* kbw  = (const float*)d_in[8];
    const float* ksw  = (const float*)d_in[9];
    float* out = (float*)d_out;

    k1_gemm<<<dim3(NG / 128, M_ / 128), 256>>>(x, ker, bias);
    k2_sub<<<3 * B_, 256>>>(x, stk, srk, kbw, ksw);
    k3_rnn<<<128, 256>>>(rk, aw, ab, out);
}

// round 9
// speedup vs baseline: 1.0942x; 1.0329x over previous
#include <cuda_runtime.h>
#include <cstdint>
#include <math.h>

#define B_  128
#define T_  256
#define D_  256
#define U_  256
#define NG  768
#define M_  (B_ * T_)

typedef unsigned long long u64;

__device__ float g_xz[M_ * NG];        // x@kernel + bias
__device__ float g_subo[3 * B_ * T_];  // sub_out[s][b][t]

// ---------------- f32x2 helpers (FFMA2 only reachable via PTX) ------------
__device__ __forceinline__ u64 pack2(float lo, float hi) {
    u64 r;
    asm("mov.b64 %0, {%1, %2};" : "=l"(r)
        : "r"(__float_as_uint(lo)), "r"(__float_as_uint(hi)));
    return r;
}
__device__ __forceinline__ u64 fma2(u64 a, u64 b, u64 c) {
    u64 d;
    asm("fma.rn.f32x2 %0, %1, %2, %3;" : "=l"(d) : "l"(a), "l"(b), "l"(c));
    return d;
}
__device__ __forceinline__ float2 unpack2(u64 v) {
    uint32_t lo, hi;
    asm("mov.b64 {%0, %1}, %2;" : "=r"(lo), "=r"(hi) : "l"(v));
    return make_float2(__uint_as_float(lo), __uint_as_float(hi));
}
__device__ __forceinline__ uint32_t smem_u32(const void* p) {
    uint32_t a;
    asm("{ .reg .u64 t; cvta.to.shared.u64 t, %1; cvt.u32.u64 %0, t; }"
        : "=r"(a) : "l"(p));
    return a;
}
__device__ __forceinline__ void st_cluster_f32(uint32_t laddr, int rank, float v) {
    uint32_t raddr;
    asm volatile("mapa.shared::cluster.u32 %0, %1, %2;"
                 : "=r"(raddr) : "r"(laddr), "r"(rank));
    asm volatile("st.shared::cluster.f32 [%0], %1;" :: "r"(raddr), "f"(v) : "memory");
}

// ---------------------------------------------------------------- k1: GEMM (f32x2)
__global__ __launch_bounds__(256, 2) void k1_gemm(const float* __restrict__ x,
                                                  const float* __restrict__ w,
                                                  const float* __restrict__ bias) {
    __shared__ __align__(16) float As[8][132];
    __shared__ __align__(16) float Bs[8][128];
    const int tid = threadIdx.x;
    const int n0 = blockIdx.x * 128, m0 = blockIdx.y * 128;
    const int tm = (tid >> 4) * 8, tn = (tid & 15) * 8;
    const int mA = tid >> 1, kq = (tid & 1) * 4;
    const int rB = tid >> 5, cB = (tid & 31) * 4;

    u64 acc2[4][8];
#pragma unroll
    for (int p = 0; p < 4; p++)
#pragma unroll
        for (int j = 0; j < 8; j++) acc2[p][j] = 0ull;

    for (int k0 = 0; k0 < 256; k0 += 8) {
        __syncthreads();
        float4 av = *reinterpret_cast<const float4*>(&x[(m0 + mA) * 256 + k0 + kq]);
        As[kq + 0][mA] = av.x; As[kq + 1][mA] = av.y;
        As[kq + 2][mA] = av.z; As[kq + 3][mA] = av.w;
        *reinterpret_cast<float4*>(&Bs[rB][cB]) =
            *reinterpret_cast<const float4*>(&w[(k0 + rB) * NG + n0 + cB]);
        __syncthreads();
#pragma unroll
        for (int k = 0; k < 8; k++) {
            const ulonglong2* ap = reinterpret_cast<const ulonglong2*>(&As[k][tm]);
            const ulonglong2 aA = ap[0], aB = ap[1];
            const u64 a2[4] = {aA.x, aA.y, aB.x, aB.y};
            float b[8];
            *reinterpret_cast<float4*>(b)     = *reinterpret_cast<float4*>(&Bs[k][tn]);
            *reinterpret_cast<float4*>(b + 4) = *reinterpret_cast<float4*>(&Bs[k][tn + 4]);
            u64 b2[8];
#pragma unroll
            for (int j = 0; j < 8; j++) b2[j] = pack2(b[j], b[j]);
#pragma unroll
            for (int p = 0; p < 4; p++)
#pragma unroll
                for (int j = 0; j < 8; j++) acc2[p][j] = fma2(a2[p], b2[j], acc2[p][j]);
        }
    }
    float bi[8];
    *reinterpret_cast<float4*>(bi)     = *reinterpret_cast<const float4*>(&bias[n0 + tn]);
    *reinterpret_cast<float4*>(bi + 4) = *reinterpret_cast<const float4*>(&bias[n0 + tn + 4]);
#pragma unroll
    for (int p = 0; p < 4; p++) {
        float r0[8], r1[8];
#pragma unroll
        for (int j = 0; j < 8; j++) {
            float2 v = unpack2(acc2[p][j]);
            r0[j] = v.x + bi[j];
            r1[j] = v.y + bi[j];
        }
        float* d0 = &g_xz[(size_t)(m0 + tm + 2 * p) * NG + n0 + tn];
        float* d1 = d0 + NG;
#pragma unroll
        for (int j = 0; j < 8; j++) { d0[j] = r0[j]; d1[j] = r1[j]; }
    }
}

// ---------------------------------------------------------------- k2: sub-TKAN/KAN
__global__ __launch_bounds__(256) void k2_sub(const float* __restrict__ x,
                                              const float* __restrict__ stk,
                                              const float* __restrict__ srk,
                                              const float* __restrict__ kbw,
                                              const float* __restrict__ ksw) {
    __shared__ float sw[256 * 9];
    __shared__ float wpart[8];
    __shared__ float bcast;
    const int s = blockIdx.x >> 7, b = blockIdx.x & 127;
    const int d = threadIdx.x, lane = d & 31, wid = d >> 5;

    const float skx = srk[s * 512 + d];
    const float skh = srk[s * 512 + 256 + d];
    const float bw  = kbw[s * 256 + d];
    const float rh  = stk[s * 2 + 0];
    const float rx  = stk[s * 2 + 1];
#pragma unroll
    for (int c = 0; c < 8; c++) sw[d * 9 + c] = ksw[(s * 256 + d) * 8 + c];
    __syncthreads();

    float sub = 0.f;
    const float* xp = x + (b * T_) * D_ + d;
    float* so = g_subo + (s * B_ + b) * T_;

    for (int t = 0; t < T_; t++) {
        const float v = xp[t * D_] * skx + sub * skh;
        float e = (v / (1.f + expf(-v))) * bw;
        const float xg = (v + 2.2f) * 2.5f;
        const float fj = floorf(xg);
        const int j = (int)fj;
        if (j >= 0 && j <= 10) {
            const float wl = xg - fj, w2 = wl * wl, w3 = w2 * wl;
            const float omw = 1.f - wl;
            const float n0 = (1.f / 6.f) * omw * omw * omw;
            const float n1 = (1.f / 6.f) * (3.f * w3 - 6.f * w2 + 4.f);
            const float n2 = (1.f / 6.f) * (-3.f * w3 + 3.f * w2 + 3.f * wl + 1.f);
            const float n3 = (1.f / 6.f) * w3;
            const int c0 = j - 3;
            const float* swd = &sw[d * 9];
            if (c0     >= 0 && c0     < 8) e += n0 * swd[c0];
            if (c0 + 1 >= 0 && c0 + 1 < 8) e += n1 * swd[c0 + 1];
            if (c0 + 2 >= 0 && c0 + 2 < 8) e += n2 * swd[c0 + 2];
            if (c0 + 3 >= 0 && c0 + 3 < 8) e += n3 * swd[c0 + 3];
        }
#pragma unroll
        for (int off = 16; off > 0; off >>= 1) e += __shfl_xor_sync(0xffffffffu, e, off);
        if (lane == 0) wpart[wid] = e;
        __syncthreads();
        if (d == 0) {
            float tot = 0.f;
#pragma unroll
            for (int ww = 0; ww < 8; ww++) tot += wpart[ww];
            so[t] = tot;
            bcast = rh * tot + rx * sub;
        }
        __syncthreads();
        sub = bcast;
    }
}

// ---------------------------------------------------------------- k3: recurrence
// 128 CTAs x 512 threads, cluster 8 (cluster = 8 batches; rank = utile of 32 u).
// Compute role: 16 warps, k-slice 16 each (4 warps/SMSP for latency hiding).
// Gate role: warps 0-7, thread owns cell (b=wid, u=u0+lane); h via DSMEM push.
__global__ __launch_bounds__(512, 1) __cluster_dims__(8, 1, 1)
void k3_rnn(const float* __restrict__ rk,   // (256,768)
            const float* __restrict__ aw,   // (3,256)
            const float* __restrict__ ab,   // (256)
            float* __restrict__ out) {      // (B,T,U)
    __shared__ __align__(16) float hs[2][2048];      // [buf][b_local*256 + k]
    __shared__ float red[256 * 51];                  // (b*32+u)*51 + gate*16 + kg
    const int tid = threadIdx.x;
    const int wid = tid >> 5, lane = tid & 31;
    const int u0 = (blockIdx.x & 7) * 32;
    const int b0 = (blockIdx.x >> 3) * 8;
    const int k0 = wid * 16;

    // weights: 16 k per warp, packed in pairs along k (once)
    u64 wi2[8], wf2[8], wc2[8];
#pragma unroll
    for (int kk = 0; kk < 8; kk++) {
        const int r0 = (k0 + 2 * kk) * NG + u0 + lane;
        const int r1 = r0 + NG;
        wi2[kk] = pack2(rk[r0],       rk[r1]);
        wf2[kk] = pack2(rk[r0 + 256], rk[r1 + 256]);
        wc2[kk] = pack2(rk[r0 + 512], rk[r1 + 512]);
    }
    // gate-role constants (warps 0-7 only, but compute cheaply for all)
    const int gb = b0 + (wid & 7);
    const int gu = u0 + lane;
    const float aw0 = aw[gu], aw1 = aw[256 + gu], aw2 = aw[512 + gu];
    const float abr = ab[gu];
    const float* so0 = g_subo + (0 * B_ + gb) * T_;
    const float* so1 = g_subo + (1 * B_ + gb) * T_;
    const float* so2 = g_subo + (2 * B_ + gb) * T_;
    const float* xzp = g_xz + (size_t)(gb * T_) * NG + gu;
    float* yp = out + (size_t)(gb * T_) * U_ + gu;
    const uint32_t hw_addr0 = smem_u32(&hs[0][(wid & 7) * 256 + u0 + lane]);
    const uint32_t hw_addr1 = smem_u32(&hs[1][(wid & 7) * 256 + u0 + lane]);

    for (int i = tid; i < 2048; i += 512) hs[0][i] = 0.f;
    asm volatile("barrier.cluster.arrive.aligned;\n\t"
                 "barrier.cluster.wait.aligned;" ::: "memory");

    float c = 0.f;
    for (int t = 0; t < T_; t++) {
        const int p = t & 1;
        float xz0, xz1, xz2, s0, s1, s2;
        if (wid < 8) {   // prefetch gate inputs early (independent of hs)
            xz0 = __ldg(&xzp[(size_t)t * NG]);
            xz1 = __ldg(&xzp[(size_t)t * NG + 256]);
            xz2 = __ldg(&xzp[(size_t)t * NG + 512]);
            s0 = __ldg(&so0[t]); s1 = __ldg(&so1[t]); s2 = __ldg(&so2[t]);
        }

        // compute role: all 16 warps; h pairs from LDS.128 halves (broadcast)
#pragma unroll
        for (int b = 0; b < 8; b++) {
            u64 ai = 0ull, af = 0ull, ac = 0ull;
            const ulonglong2* hp =
                reinterpret_cast<const ulonglong2*>(&hs[p][b * 256 + k0]);
            const ulonglong2 h0 = hp[0], h1 = hp[1];
            ai = fma2(h0.x, wi2[0], ai); af = fma2(h0.x, wf2[0], af); ac = fma2(h0.x, wc2[0], ac);
            ai = fma2(h0.y, wi2[1], ai); af = fma2(h0.y, wf2[1], af); ac = fma2(h0.y, wc2[1], ac);
            ai = fma2(h1.x, wi2[2], ai); af = fma2(h1.x, wf2[2], af); ac = fma2(h1.x, wc2[2], ac);
            ai = fma2(h1.y, wi2[3], ai); af = fma2(h1.y, wf2[3], af); ac = fma2(h1.y, wc2[3], ac);
            const ulonglong2 h2 = hp[2], h3 = hp[3];
            ai = fma2(h2.x, wi2[4], ai); af = fma2(h2.x, wf2[4], af); ac = fma2(h2.x, wc2[4], ac);
            ai = fma2(h2.y, wi2[5], ai); af = fma2(h2.y, wf2[5], af); ac = fma2(h2.y, wc2[5], ac);
            ai = fma2(h3.x, wi2[6], ai); af = fma2(h3.x, wf2[6], af); ac = fma2(h3.x, wc2[6], ac);
            ai = fma2(h3.y, wi2[7], ai); af = fma2(h3.y, wf2[7], af); ac = fma2(h3.y, wc2[7], ac);
            const float2 vi = unpack2(ai), vf = unpack2(af), vc = unpack2(ac);
            const int base = (b * 32 + lane) * 51 + wid;   // 51 coprime w/ 32: conflict-free
            red[base]      = vi.x + vi.y;
            red[base + 16] = vf.x + vf.y;
            red[base + 32] = vc.x + vc.y;
        }
        __syncthreads();

        // gate role: warps 0-7
        if (wid < 8) {
            float zi = xz0, zf = xz1, zc = xz2;
            const int rbase = (wid * 32 + lane) * 51;
#pragma unroll
            for (int kg = 0; kg < 16; kg++) {
                zi += red[rbase + kg];
                zf += red[rbase + 16 + kg];
                zc += red[rbase + 32 + kg];
            }
            const float ig = 1.f / (1.f + expf(-zi));
            const float fg = 1.f / (1.f + expf(-zf));
            c = fg * c + ig * tanhf(zc);
            const float oarg = s0 * aw0 + s1 * aw1 + s2 * aw2 + abr;
            const float o = 1.f / (1.f + expf(-oarg));
            const float h = o * tanhf(c);

            // DSMEM broadcast h into next buffer of every cluster CTA
            const uint32_t laddr = p ? hw_addr0 : hw_addr1;
#pragma unroll
            for (int r = 0; r < 8; r++) st_cluster_f32(laddr, r, h);

            yp[(size_t)t * U_] = h;
        }

        // release my DSMEM stores / acquire peers'; also separates red
        // reads (gate) from next step's red writes (compute)
        asm volatile("barrier.cluster.arrive.aligned;\n\t"
                     "barrier.cluster.wait.aligned;" ::: "memory");
    }
}

// ---------------------------------------------------------------- launch
extern "C" void kernel_launch(void* const* d_in, const int* in_sizes, int n_in,
                              void* d_out, int out_size) {
    const float* x    = (const float*)d_in[0];
    const float* ker  = (const float*)d_in[1];
    const float* rk   = (const float*)d_in[2];
    const float* bias = (const float*)d_in[3];
    const float* stk  = (const float*)d_in[4];
    const float* srk  = (const float*)d_in[5];
    const float* aw   = (const float*)d_in[6];
    const float* ab   = (const float*)d_in[7];
    const float* kbw  = (const float*)d_in[8];
    const float* ksw  = (const float*)d_in[9];
    float* out = (float*)d_out;

    k1_gemm<<<dim3(NG / 128, M_ / 128), 256>>>(x, ker, bias);
    k2_sub<<<3 * B_, 256>>>(x, stk, srk, kbw, ksw);
    k3_rnn<<<128, 512>>>(rk, aw, ab, out);
}

// round 10
// speedup vs baseline: 1.3910x; 1.2713x over previous
#include <cuda_runtime.h>
#include <cstdint>
#include <math.h>

#define B_  128
#define T_  256
#define D_  256
#define U_  256
#define NG  768
#define M_  (B_ * T_)

typedef unsigned long long u64;

__device__ float g_xz[M_ * NG];        // x@kernel + bias
__device__ float g_subo[3 * B_ * T_];  // sub_out[s][b][t]

// ---------------- f32x2 helpers (FFMA2 only reachable via PTX) ------------
__device__ __forceinline__ u64 pack2(float lo, float hi) {
    u64 r;
    asm("mov.b64 %0, {%1, %2};" : "=l"(r)
        : "r"(__float_as_uint(lo)), "r"(__float_as_uint(hi)));
    return r;
}
__device__ __forceinline__ u64 fma2(u64 a, u64 b, u64 c) {
    u64 d;
    asm("fma.rn.f32x2 %0, %1, %2, %3;" : "=l"(d) : "l"(a), "l"(b), "l"(c));
    return d;
}
__device__ __forceinline__ float2 unpack2(u64 v) {
    uint32_t lo, hi;
    asm("mov.b64 {%0, %1}, %2;" : "=r"(lo), "=r"(hi) : "l"(v));
    return make_float2(__uint_as_float(lo), __uint_as_float(hi));
}
__device__ __forceinline__ uint32_t smem_u32(const void* p) {
    uint32_t a;
    asm("{ .reg .u64 t; cvta.to.shared.u64 t, %1; cvt.u32.u64 %0, t; }"
        : "=r"(a) : "l"(p));
    return a;
}
__device__ __forceinline__ void mbar_init(uint32_t m, uint32_t cnt) {
    asm volatile("mbarrier.init.shared.b64 [%0], %1;" :: "r"(m), "r"(cnt) : "memory");
}
__device__ __forceinline__ void mbar_arm(uint32_t m, uint32_t bytes) {
    asm volatile("mbarrier.arrive.expect_tx.shared.b64 _, [%0], %1;"
                 :: "r"(m), "r"(bytes) : "memory");
}
__device__ __forceinline__ void mbar_wait(uint32_t m, uint32_t parity) {
    asm volatile(
        "{\n\t"
        ".reg .pred P;\n\t"
        "WL%=:\n\t"
        "mbarrier.try_wait.parity.acquire.cluster.shared::cta.b64 P, [%0], %1, 0x989680;\n\t"
        "@P bra WD%=;\n\t"
        "bra WL%=;\n\t"
        "WD%=:\n\t"
        "}"
        :: "r"(m), "r"(parity) : "memory");
}
__device__ __forceinline__ void st_async_to(uint32_t laddr, uint32_t lmbar,
                                            int rank, float v) {
    uint32_t rh, rm;
    asm("mapa.shared::cluster.u32 %0, %1, %2;" : "=r"(rh) : "r"(laddr), "r"(rank));
    asm("mapa.shared::cluster.u32 %0, %1, %2;" : "=r"(rm) : "r"(lmbar), "r"(rank));
    asm volatile(
        "st.async.shared::cluster.mbarrier::complete_tx::bytes.b32 [%0], %1, [%2];"
        :: "r"(rh), "r"(__float_as_uint(v)), "r"(rm) : "memory");
}

// ---------------------------------------------------------------- k1: GEMM (f32x2)
__global__ __launch_bounds__(256, 2) void k1_gemm(const float* __restrict__ x,
                                                  const float* __restrict__ w,
                                                  const float* __restrict__ bias) {
    __shared__ __align__(16) float As[8][132];
    __shared__ __align__(16) float Bs[8][128];
    const int tid = threadIdx.x;
    const int n0 = blockIdx.x * 128, m0 = blockIdx.y * 128;
    const int tm = (tid >> 4) * 8, tn = (tid & 15) * 8;
    const int mA = tid >> 1, kq = (tid & 1) * 4;
    const int rB = tid >> 5, cB = (tid & 31) * 4;

    u64 acc2[4][8];
#pragma unroll
    for (int p = 0; p < 4; p++)
#pragma unroll
        for (int j = 0; j < 8; j++) acc2[p][j] = 0ull;

    for (int k0 = 0; k0 < 256; k0 += 8) {
        __syncthreads();
        float4 av = *reinterpret_cast<const float4*>(&x[(m0 + mA) * 256 + k0 + kq]);
        As[kq + 0][mA] = av.x; As[kq + 1][mA] = av.y;
        As[kq + 2][mA] = av.z; As[kq + 3][mA] = av.w;
        *reinterpret_cast<float4*>(&Bs[rB][cB]) =
            *reinterpret_cast<const float4*>(&w[(k0 + rB) * NG + n0 + cB]);
        __syncthreads();
#pragma unroll
        for (int k = 0; k < 8; k++) {
            const ulonglong2* ap = reinterpret_cast<const ulonglong2*>(&As[k][tm]);
            const ulonglong2 aA = ap[0], aB = ap[1];
            const u64 a2[4] = {aA.x, aA.y, aB.x, aB.y};
            float b[8];
            *reinterpret_cast<float4*>(b)     = *reinterpret_cast<float4*>(&Bs[k][tn]);
            *reinterpret_cast<float4*>(b + 4) = *reinterpret_cast<float4*>(&Bs[k][tn + 4]);
            u64 b2[8];
#pragma unroll
            for (int j = 0; j < 8; j++) b2[j] = pack2(b[j], b[j]);
#pragma unroll
            for (int p = 0; p < 4; p++)
#pragma unroll
                for (int j = 0; j < 8; j++) acc2[p][j] = fma2(a2[p], b2[j], acc2[p][j]);
        }
    }
    float bi[8];
    *reinterpret_cast<float4*>(bi)     = *reinterpret_cast<const float4*>(&bias[n0 + tn]);
    *reinterpret_cast<float4*>(bi + 4) = *reinterpret_cast<const float4*>(&bias[n0 + tn + 4]);
#pragma unroll
    for (int p = 0; p < 4; p++) {
        float r0[8], r1[8];
#pragma unroll
        for (int j = 0; j < 8; j++) {
            float2 v = unpack2(acc2[p][j]);
            r0[j] = v.x + bi[j];
            r1[j] = v.y + bi[j];
        }
        float* d0 = &g_xz[(size_t)(m0 + tm + 2 * p) * NG + n0 + tn];
        float* d1 = d0 + NG;
#pragma unroll
        for (int j = 0; j < 8; j++) { d0[j] = r0[j]; d1[j] = r1[j]; }
    }
}

// ---------------------------------------------------------------- k2: sub-TKAN/KAN
__global__ __launch_bounds__(256) void k2_sub(const float* __restrict__ x,
                                              const float* __restrict__ stk,
                                              const float* __restrict__ srk,
                                              const float* __restrict__ kbw,
                                              const float* __restrict__ ksw) {
    __shared__ float sw[256 * 9];
    __shared__ float wpart[8];
    __shared__ float bcast;
    const int s = blockIdx.x >> 7, b = blockIdx.x & 127;
    const int d = threadIdx.x, lane = d & 31, wid = d >> 5;

    const float skx = srk[s * 512 + d];
    const float skh = srk[s * 512 + 256 + d];
    const float bw  = kbw[s * 256 + d];
    const float rh  = stk[s * 2 + 0];
    const float rx  = stk[s * 2 + 1];
#pragma unroll
    for (int c = 0; c < 8; c++) sw[d * 9 + c] = ksw[(s * 256 + d) * 8 + c];
    __syncthreads();

    float sub = 0.f;
    const float* xp = x + (b * T_) * D_ + d;
    float* so = g_subo + (s * B_ + b) * T_;

    for (int t = 0; t < T_; t++) {
        const float v = xp[t * D_] * skx + sub * skh;
        float e = (v / (1.f + expf(-v))) * bw;
        const float xg = (v + 2.2f) * 2.5f;
        const float fj = floorf(xg);
        const int j = (int)fj;
        if (j >= 0 && j <= 10) {
            const float wl = xg - fj, w2 = wl * wl, w3 = w2 * wl;
            const float omw = 1.f - wl;
            const float n0 = (1.f / 6.f) * omw * omw * omw;
            const float n1 = (1.f / 6.f) * (3.f * w3 - 6.f * w2 + 4.f);
            const float n2 = (1.f / 6.f) * (-3.f * w3 + 3.f * w2 + 3.f * wl + 1.f);
            const float n3 = (1.f / 6.f) * w3;
            const int c0 = j - 3;
            const float* swd = &sw[d * 9];
            if (c0     >= 0 && c0     < 8) e += n0 * swd[c0];
            if (c0 + 1 >= 0 && c0 + 1 < 8) e += n1 * swd[c0 + 1];
            if (c0 + 2 >= 0 && c0 + 2 < 8) e += n2 * swd[c0 + 2];
            if (c0 + 3 >= 0 && c0 + 3 < 8) e += n3 * swd[c0 + 3];
        }
#pragma unroll
        for (int off = 16; off > 0; off >>= 1) e += __shfl_xor_sync(0xffffffffu, e, off);
        if (lane == 0) wpart[wid] = e;
        __syncthreads();
        if (d == 0) {
            float tot = 0.f;
#pragma unroll
            for (int ww = 0; ww < 8; ww++) tot += wpart[ww];
            so[t] = tot;
            bcast = rh * tot + rx * sub;
        }
        __syncthreads();
        sub = bcast;
    }
}

// ---------------------------------------------------------------- k3: recurrence
// 128 CTAs x 512 threads, cluster 8 (= 8 batches; rank = 32-u tile).
// Sync is pure data-flow: h delivered by st.async with mbarrier tx-counting
// (8192 B/step/CTA). No cluster barrier in the loop; gate inputs prefetched
// one step ahead so DRAM latency hides under the mbarrier wait.
__global__ __launch_bounds__(512, 1) __cluster_dims__(8, 1, 1)
void k3_rnn(const float* __restrict__ rk,   // (256,768)
            const float* __restrict__ aw,   // (3,256)
            const float* __restrict__ ab,   // (256)
            float* __restrict__ out) {      // (B,T,U)
    __shared__ __align__(16) float hs[2][2048];      // [buf][b_local*256 + k]
    __shared__ float red[256 * 51];
    __shared__ __align__(8) unsigned long long mbar_s[2];
    const int tid = threadIdx.x;
    const int wid = tid >> 5, lane = tid & 31;
    const int u0 = (blockIdx.x & 7) * 32;
    const int b0 = (blockIdx.x >> 3) * 8;
    const int k0 = wid * 16;

    const uint32_t mb0 = smem_u32(&mbar_s[0]);
    const uint32_t mb1 = smem_u32(&mbar_s[1]);

    // weights: 16 k per warp, packed in pairs along k (once)
    u64 wi2[8], wf2[8], wc2[8];
#pragma unroll
    for (int kk = 0; kk < 8; kk++) {
        const int r0 = (k0 + 2 * kk) * NG + u0 + lane;
        const int r1 = r0 + NG;
        wi2[kk] = pack2(rk[r0],       rk[r1]);
        wf2[kk] = pack2(rk[r0 + 256], rk[r1 + 256]);
        wc2[kk] = pack2(rk[r0 + 512], rk[r1 + 512]);
    }
    // gate-role constants (warps 0-7)
    const int gb = b0 + (wid & 7);
    const int gu = u0 + lane;
    const float aw0 = aw[gu], aw1 = aw[256 + gu], aw2 = aw[512 + gu];
    const float abr = ab[gu];
    const float* so0 = g_subo + (0 * B_ + gb) * T_;
    const float* so1 = g_subo + (1 * B_ + gb) * T_;
    const float* so2 = g_subo + (2 * B_ + gb) * T_;
    const float* xzp = g_xz + (size_t)(gb * T_) * NG + gu;
    float* yp = out + (size_t)(gb * T_) * U_ + gu;
    const uint32_t hw_addr0 = smem_u32(&hs[0][(wid & 7) * 256 + u0 + lane]);
    const uint32_t hw_addr1 = smem_u32(&hs[1][(wid & 7) * 256 + u0 + lane]);

    // init: mbarriers (count 1) pre-armed for their first phase, hs[0]=0
    if (tid == 0) {
        mbar_init(mb0, 1);
        mbar_init(mb1, 1);
        mbar_arm(mb0, 8192);
        mbar_arm(mb1, 8192);
    }
    for (int i = tid; i < 2048; i += 512) hs[0][i] = 0.f;
    __syncthreads();
    asm volatile("barrier.cluster.arrive.aligned;\n\t"
                 "barrier.cluster.wait.aligned;" ::: "memory");

    // prefetch gate inputs for t=0
    float xz0, xz1, xz2, s0, s1, s2;
    if (wid < 8) {
        xz0 = __ldg(&xzp[0]);
        xz1 = __ldg(&xzp[256]);
        xz2 = __ldg(&xzp[512]);
        s0 = __ldg(&so0[0]); s1 = __ldg(&so1[0]); s2 = __ldg(&so2[0]);
    }

    float c = 0.f;
    for (int t = 0; t < T_; t++) {
        const int p = t & 1;
        if (t > 0) {
            const uint32_t m = p ? mb1 : mb0;
            mbar_wait(m, ((t - 1) >> 1) & 1);
            if (tid == 0) mbar_arm(m, 8192);   // re-arm for next use (step t+1 sends)
        }

        // compute role: all 16 warps; h pairs from LDS.128 halves (broadcast)
#pragma unroll
        for (int b = 0; b < 8; b++) {
            u64 ai = 0ull, af = 0ull, ac = 0ull;
            const ulonglong2* hp =
                reinterpret_cast<const ulonglong2*>(&hs[p][b * 256 + k0]);
            const ulonglong2 h0 = hp[0], h1 = hp[1];
            ai = fma2(h0.x, wi2[0], ai); af = fma2(h0.x, wf2[0], af); ac = fma2(h0.x, wc2[0], ac);
            ai = fma2(h0.y, wi2[1], ai); af = fma2(h0.y, wf2[1], af); ac = fma2(h0.y, wc2[1], ac);
            ai = fma2(h1.x, wi2[2], ai); af = fma2(h1.x, wf2[2], af); ac = fma2(h1.x, wc2[2], ac);
            ai = fma2(h1.y, wi2[3], ai); af = fma2(h1.y, wf2[3], af); ac = fma2(h1.y, wc2[3], ac);
            const ulonglong2 h2 = hp[2], h3 = hp[3];
            ai = fma2(h2.x, wi2[4], ai); af = fma2(h2.x, wf2[4], af); ac = fma2(h2.x, wc2[4], ac);
            ai = fma2(h2.y, wi2[5], ai); af = fma2(h2.y, wf2[5], af); ac = fma2(h2.y, wc2[5], ac);
            ai = fma2(h3.x, wi2[6], ai); af = fma2(h3.x, wf2[6], af); ac = fma2(h3.x, wc2[6], ac);
            ai = fma2(h3.y, wi2[7], ai); af = fma2(h3.y, wf2[7], af); ac = fma2(h3.y, wc2[7], ac);
            const float2 vi = unpack2(ai), vf = unpack2(af), vc = unpack2(ac);
            const int base = (b * 32 + lane) * 51 + wid;   // 51 coprime w/ 32: conflict-free
            red[base]      = vi.x + vi.y;
            red[base + 16] = vf.x + vf.y;
            red[base + 32] = vc.x + vc.y;
        }
        __syncthreads();

        // gate role: warps 0-7
        if (wid < 8) {
            float zi = xz0, zf = xz1, zc = xz2;
            const int rbase = (wid * 32 + lane) * 51;
#pragma unroll
            for (int kg = 0; kg < 16; kg++) {
                zi += red[rbase + kg];
                zf += red[rbase + 16 + kg];
                zc += red[rbase + 32 + kg];
            }
            const float ig = 1.f / (1.f + expf(-zi));
            const float fg = 1.f / (1.f + expf(-zf));
            c = fg * c + ig * tanhf(zc);
            const float oarg = s0 * aw0 + s1 * aw1 + s2 * aw2 + abr;
            const float o = 1.f / (1.f + expf(-oarg));
            const float h = o * tanhf(c);

            if (t < T_ - 1) {
                // deliver h into next buffer of every cluster CTA (tx-counted)
                const uint32_t lh = p ? hw_addr0 : hw_addr1;
                const uint32_t lm = p ? mb0 : mb1;
#pragma unroll
                for (int r = 0; r < 8; r++) st_async_to(lh, lm, r, h);
            }
            yp[(size_t)t * U_] = h;

            if (t < T_ - 1) {   // prefetch next step's gate inputs under the wait
                const size_t o1 = (size_t)(t + 1) * NG;
                xz0 = __ldg(&xzp[o1]);
                xz1 = __ldg(&xzp[o1 + 256]);
                xz2 = __ldg(&xzp[o1 + 512]);
                s0 = __ldg(&so0[t + 1]); s1 = __ldg(&so1[t + 1]); s2 = __ldg(&so2[t + 1]);
            }
        }
    }
    asm volatile("barrier.cluster.arrive.aligned;\n\t"
                 "barrier.cluster.wait.aligned;" ::: "memory");
}

// ---------------------------------------------------------------- launch
extern "C" void kernel_launch(void* const* d_in, const int* in_sizes, int n_in,
                              void* d_out, int out_size) {
    const float* x    = (const float*)d_in[0];
    const float* ker  = (const float*)d_in[1];
    const float* rk   = (const float*)d_in[2];
    const float* bias = (const float*)d_in[3];
    const float* stk  = (const float*)d_in[4];
    const float* srk  = (const float*)d_in[5];
    const float* aw   = (const float*)d_in[6];
    const float* ab   = (const float*)d_in[7];
    const float* kbw  = (const float*)d_in[8];
    const float* ksw  = (const float*)d_in[9];
    float* out = (float*)d_out;

    k1_gemm<<<dim3(NG / 128, M_ / 128), 256>>>(x, ker, bias);
    k2_sub<<<3 * B_, 256>>>(x, stk, srk, kbw, ksw);
    k3_rnn<<<128, 512>>>(rk, aw, ab, out);
}

// round 11
// speedup vs baseline: 1.5307x; 1.1004x over previous
#include <cuda_runtime.h>
#include <cstdint>
#include <math.h>

#define B_  128
#define T_  256
#define D_  256
#define U_  256
#define NG  768
#define M_  (B_ * T_)

typedef unsigned long long u64;

__device__ float g_xz[M_ * NG];        // x@kernel + bias
__device__ float g_subo[3 * B_ * T_];  // sub_out[s][b][t]

// ---------------- helpers ------------------------------------------------
__device__ __forceinline__ u64 pack2(float lo, float hi) {
    u64 r;
    asm("mov.b64 %0, {%1, %2};" : "=l"(r)
        : "r"(__float_as_uint(lo)), "r"(__float_as_uint(hi)));
    return r;
}
__device__ __forceinline__ u64 fma2(u64 a, u64 b, u64 c) {
    u64 d;
    asm("fma.rn.f32x2 %0, %1, %2, %3;" : "=l"(d) : "l"(a), "l"(b), "l"(c));
    return d;
}
__device__ __forceinline__ float2 unpack2(u64 v) {
    uint32_t lo, hi;
    asm("mov.b64 {%0, %1}, %2;" : "=r"(lo), "=r"(hi) : "l"(v));
    return make_float2(__uint_as_float(lo), __uint_as_float(hi));
}
__device__ __forceinline__ uint32_t smem_u32(const void* p) {
    uint32_t a;
    asm("{ .reg .u64 t; cvta.to.shared.u64 t, %1; cvt.u32.u64 %0, t; }"
        : "=r"(a) : "l"(p));
    return a;
}
__device__ __forceinline__ void mbar_init(uint32_t m, uint32_t cnt) {
    asm volatile("mbarrier.init.shared.b64 [%0], %1;" :: "r"(m), "r"(cnt) : "memory");
}
__device__ __forceinline__ void mbar_arm(uint32_t m, uint32_t bytes) {
    asm volatile("mbarrier.arrive.expect_tx.shared.b64 _, [%0], %1;"
                 :: "r"(m), "r"(bytes) : "memory");
}
__device__ __forceinline__ void mbar_wait(uint32_t m, uint32_t parity) {
    asm volatile(
        "{\n\t"
        ".reg .pred P;\n\t"
        "WL%=:\n\t"
        "mbarrier.try_wait.parity.acquire.cluster.shared::cta.b64 P, [%0], %1, 0x989680;\n\t"
        "@P bra WD%=;\n\t"
        "bra WL%=;\n\t"
        "WD%=:\n\t"
        "}"
        :: "r"(m), "r"(parity) : "memory");
}
__device__ __forceinline__ uint32_t mapa_u32(uint32_t laddr, int rank) {
    uint32_t r;
    asm("mapa.shared::cluster.u32 %0, %1, %2;" : "=r"(r) : "r"(laddr), "r"(rank));
    return r;
}
__device__ __forceinline__ void st_async_b64(uint32_t raddr, u64 v, uint32_t rmbar) {
    asm volatile(
        "st.async.shared::cluster.mbarrier::complete_tx::bytes.b64 [%0], %1, [%2];"
        :: "r"(raddr), "l"(v), "r"(rmbar) : "memory");
}
// fast transcendentals (MUFU-based; rel err ~1e-6, far under 1e-3 budget)
__device__ __forceinline__ float fast_sig(float x) {
    return __fdividef(1.f, 1.f + __expf(-x));
}
__device__ __forceinline__ float fast_tanh(float x) {
    // 1 - 2/(e^{2x}+1): no overflow (e^{2x}->inf => 1), no NaN
    return 1.f - __fdividef(2.f, __expf(2.f * x) + 1.f);
}

// ---------------------------------------------------------------- k1: GEMM
// register-staged double buffering: one __syncthreads per k-tile, LDG for
// tile i+1 issued before compute of tile i.
__global__ __launch_bounds__(256, 2) void k1_gemm(const float* __restrict__ x,
                                                  const float* __restrict__ w,
                                                  const float* __restrict__ bias) {
    __shared__ __align__(16) float As[2][8][132];
    __shared__ __align__(16) float Bs[2][8][128];
    const int tid = threadIdx.x;
    const int n0 = blockIdx.x * 128, m0 = blockIdx.y * 128;
    const int tm = (tid >> 4) * 8, tn = (tid & 15) * 8;
    const int mA = tid >> 1, kq = (tid & 1) * 4;
    const int rB = tid >> 5, cB = (tid & 31) * 4;

    u64 acc2[4][8];
#pragma unroll
    for (int p = 0; p < 4; p++)
#pragma unroll
        for (int j = 0; j < 8; j++) acc2[p][j] = 0ull;

    // prologue: LDG tile 0 into registers
    float4 av = *reinterpret_cast<const float4*>(&x[(m0 + mA) * 256 + kq]);
    float4 bv = *reinterpret_cast<const float4*>(&w[rB * NG + n0 + cB]);

    for (int k0 = 0; k0 < 256; k0 += 8) {
        const int cur = (k0 >> 3) & 1;
        // stage current tile (safe: this buffer was last read 2 tiles ago)
        As[cur][kq + 0][mA] = av.x; As[cur][kq + 1][mA] = av.y;
        As[cur][kq + 2][mA] = av.z; As[cur][kq + 3][mA] = av.w;
        *reinterpret_cast<float4*>(&Bs[cur][rB][cB]) = bv;
        __syncthreads();
        // prefetch next tile (latency hidden under compute below)
        if (k0 + 8 < 256) {
            av = *reinterpret_cast<const float4*>(&x[(m0 + mA) * 256 + k0 + 8 + kq]);
            bv = *reinterpret_cast<const float4*>(&w[(k0 + 8 + rB) * NG + n0 + cB]);
        }
#pragma unroll
        for (int k = 0; k < 8; k++) {
            const ulonglong2* ap = reinterpret_cast<const ulonglong2*>(&As[cur][k][tm]);
            const ulonglong2 aA = ap[0], aB = ap[1];
            const u64 a2[4] = {aA.x, aA.y, aB.x, aB.y};
            float b[8];
            *reinterpret_cast<float4*>(b)     = *reinterpret_cast<float4*>(&Bs[cur][k][tn]);
            *reinterpret_cast<float4*>(b + 4) = *reinterpret_cast<float4*>(&Bs[cur][k][tn + 4]);
            u64 b2[8];
#pragma unroll
            for (int j = 0; j < 8; j++) b2[j] = pack2(b[j], b[j]);
#pragma unroll
            for (int p = 0; p < 4; p++)
#pragma unroll
                for (int j = 0; j < 8; j++) acc2[p][j] = fma2(a2[p], b2[j], acc2[p][j]);
        }
    }
    float bi[8];
    *reinterpret_cast<float4*>(bi)     = *reinterpret_cast<const float4*>(&bias[n0 + tn]);
    *reinterpret_cast<float4*>(bi + 4) = *reinterpret_cast<const float4*>(&bias[n0 + tn + 4]);
#pragma unroll
    for (int p = 0; p < 4; p++) {
        float r0[8], r1[8];
#pragma unroll
        for (int j = 0; j < 8; j++) {
            float2 v = unpack2(acc2[p][j]);
            r0[j] = v.x + bi[j];
            r1[j] = v.y + bi[j];
        }
        float* d0 = &g_xz[(size_t)(m0 + tm + 2 * p) * NG + n0 + tn];
        float* d1 = d0 + NG;
#pragma unroll
        for (int j = 0; j < 8; j++) { d0[j] = r0[j]; d1[j] = r1[j]; }
    }
}

// ---------------------------------------------------------------- k2: sub-TKAN/KAN
__global__ __launch_bounds__(256) void k2_sub(const float* __restrict__ x,
                                              const float* __restrict__ stk,
                                              const float* __restrict__ srk,
                                              const float* __restrict__ kbw,
                                              const float* __restrict__ ksw) {
    __shared__ float sw[256 * 9];
    __shared__ float wpart[8];
    __shared__ float bcast;
    const int s = blockIdx.x >> 7, b = blockIdx.x & 127;
    const int d = threadIdx.x, lane = d & 31, wid = d >> 5;

    const float skx = srk[s * 512 + d];
    const float skh = srk[s * 512 + 256 + d];
    const float bw  = kbw[s * 256 + d];
    const float rh  = stk[s * 2 + 0];
    const float rx  = stk[s * 2 + 1];
#pragma unroll
    for (int c = 0; c < 8; c++) sw[d * 9 + c] = ksw[(s * 256 + d) * 8 + c];
    __syncthreads();

    float sub = 0.f;
    const float* xp = x + (b * T_) * D_ + d;
    float* so = g_subo + (s * B_ + b) * T_;

    float xv = __ldg(&xp[0]);                      // prefetched x_t
    for (int t = 0; t < T_; t++) {
        const float xn = (t < T_ - 1) ? __ldg(&xp[(t + 1) * D_]) : 0.f;  // hide DRAM
        const float v = xv * skx + sub * skh;
        float e = v * fast_sig(v) * bw;            // silu * base_w
        const float xg = (v + 2.2f) * 2.5f;
        const float fj = floorf(xg);
        const int j = (int)fj;
        if (j >= 0 && j <= 10) {
            const float wl = xg - fj, w2 = wl * wl, w3 = w2 * wl;
            const float omw = 1.f - wl;
            const float n0 = (1.f / 6.f) * omw * omw * omw;
            const float n1 = (1.f / 6.f) * (3.f * w3 - 6.f * w2 + 4.f);
            const float n2 = (1.f / 6.f) * (-3.f * w3 + 3.f * w2 + 3.f * wl + 1.f);
            const float n3 = (1.f / 6.f) * w3;
            const int c0 = j - 3;
            const float* swd = &sw[d * 9];
            if (c0     >= 0 && c0     < 8) e += n0 * swd[c0];
            if (c0 + 1 >= 0 && c0 + 1 < 8) e += n1 * swd[c0 + 1];
            if (c0 + 2 >= 0 && c0 + 2 < 8) e += n2 * swd[c0 + 2];
            if (c0 + 3 >= 0 && c0 + 3 < 8) e += n3 * swd[c0 + 3];
        }
#pragma unroll
        for (int off = 16; off > 0; off >>= 1) e += __shfl_xor_sync(0xffffffffu, e, off);
        if (lane == 0) wpart[wid] = e;
        __syncthreads();
        if (d == 0) {
            float tot = 0.f;
#pragma unroll
            for (int ww = 0; ww < 8; ww++) tot += wpart[ww];
            so[t] = tot;
            bcast = rh * tot + rx * sub;
        }
        __syncthreads();
        sub = bcast;
        xv = xn;
    }
}

// ---------------------------------------------------------------- k3: recurrence
// 128 CTAs x 512 threads, cluster 8 (= 8 batches; rank = 32-u tile).
// Data-flow sync: h delivered via st.async.b64 (paired lanes) with mbarrier
// tx-counting (8192 B/step/CTA). mapa addresses hoisted out of the loop.
__global__ __launch_bounds__(512, 1) __cluster_dims__(8, 1, 1)
void k3_rnn(const float* __restrict__ rk,   // (256,768)
            const float* __restrict__ aw,   // (3,256)
            const float* __restrict__ ab,   // (256)
            float* __restrict__ out) {      // (B,T,U)
    __shared__ __align__(16) float hs[2][2048];      // [buf][b_local*256 + k]
    __shared__ float red[256 * 51];
    __shared__ __align__(8) unsigned long long mbar_s[2];
    const int tid = threadIdx.x;
    const int wid = tid >> 5, lane = tid & 31;
    const int u0 = (blockIdx.x & 7) * 32;
    const int b0 = (blockIdx.x >> 3) * 8;
    const int k0 = wid * 16;

    const uint32_t mb0 = smem_u32(&mbar_s[0]);
    const uint32_t mb1 = smem_u32(&mbar_s[1]);

    // weights: 16 k per warp, packed in pairs along k (once)
    u64 wi2[8], wf2[8], wc2[8];
#pragma unroll
    for (int kk = 0; kk < 8; kk++) {
        const int r0 = (k0 + 2 * kk) * NG + u0 + lane;
        const int r1 = r0 + NG;
        wi2[kk] = pack2(rk[r0],       rk[r1]);
        wf2[kk] = pack2(rk[r0 + 256], rk[r1 + 256]);
        wc2[kk] = pack2(rk[r0 + 512], rk[r1 + 512]);
    }
    // gate-role constants (warps 0-7)
    const int gb = b0 + (wid & 7);
    const int gu = u0 + lane;
    const float aw0 = aw[gu], aw1 = aw[256 + gu], aw2 = aw[512 + gu];
    const float abr = ab[gu];
    const float* so0 = g_subo + (0 * B_ + gb) * T_;
    const float* so1 = g_subo + (1 * B_ + gb) * T_;
    const float* so2 = g_subo + (2 * B_ + gb) * T_;
    const float* xzp = g_xz + (size_t)(gb * T_) * NG + gu;
    float* yp = out + (size_t)(gb * T_) * U_ + gu;

    // hoisted remote addresses (even lanes send b64 pairs).
    // parity-1 buffer = parity-0 addr + 8192; mb1 = mb0 addr + 8.
    uint32_t rh0[8], rm0[8];
    {
        const uint32_t lh = smem_u32(&hs[0][(wid & 7) * 256 + u0 + lane]);
#pragma unroll
        for (int r = 0; r < 8; r++) {
            rh0[r] = mapa_u32(lh, r);
            rm0[r] = mapa_u32(mb0, r);
        }
    }

    if (tid == 0) {
        mbar_init(mb0, 1);
        mbar_init(mb1, 1);
        mbar_arm(mb0, 8192);
        mbar_arm(mb1, 8192);
    }
    for (int i = tid; i < 2048; i += 512) hs[0][i] = 0.f;
    __syncthreads();
    asm volatile("barrier.cluster.arrive.aligned;\n\t"
                 "barrier.cluster.wait.aligned;" ::: "memory");

    // prefetch gate inputs for t=0
    float xz0, xz1, xz2, s0, s1, s2;
    if (wid < 8) {
        xz0 = __ldg(&xzp[0]);
        xz1 = __ldg(&xzp[256]);
        xz2 = __ldg(&xzp[512]);
        s0 = __ldg(&so0[0]); s1 = __ldg(&so1[0]); s2 = __ldg(&so2[0]);
    }

    float c = 0.f;
    for (int t = 0; t < T_; t++) {
        const int p = t & 1;
        if (t > 0) {
            const uint32_t m = p ? mb1 : mb0;
            mbar_wait(m, ((t - 1) >> 1) & 1);
            if (tid == 0) mbar_arm(m, 8192);   // re-arm for step t+1 sends
        }

        // compute role: all 16 warps; h pairs from LDS.128 halves (broadcast)
#pragma unroll
        for (int b = 0; b < 8; b++) {
            u64 ai = 0ull, af = 0ull, ac = 0ull;
            const ulonglong2* hp =
                reinterpret_cast<const ulonglong2*>(&hs[p][b * 256 + k0]);
            const ulonglong2 h0 = hp[0], h1 = hp[1];
            ai = fma2(h0.x, wi2[0], ai); af = fma2(h0.x, wf2[0], af); ac = fma2(h0.x, wc2[0], ac);
            ai = fma2(h0.y, wi2[1], ai); af = fma2(h0.y, wf2[1], af); ac = fma2(h0.y, wc2[1], ac);
            ai = fma2(h1.x, wi2[2], ai); af = fma2(h1.x, wf2[2], af); ac = fma2(h1.x, wc2[2], ac);
            ai = fma2(h1.y, wi2[3], ai); af = fma2(h1.y, wf2[3], af); ac = fma2(h1.y, wc2[3], ac);
            const ulonglong2 h2 = hp[2], h3 = hp[3];
            ai = fma2(h2.x, wi2[4], ai); af = fma2(h2.x, wf2[4], af); ac = fma2(h2.x, wc2[4], ac);
            ai = fma2(h2.y, wi2[5], ai); af = fma2(h2.y, wf2[5], af); ac = fma2(h2.y, wc2[5], ac);
            ai = fma2(h3.x, wi2[6], ai); af = fma2(h3.x, wf2[6], af); ac = fma2(h3.x, wc2[6], ac);
            ai = fma2(h3.y, wi2[7], ai); af = fma2(h3.y, wf2[7], af); ac = fma2(h3.y, wc2[7], ac);
            const float2 vi = unpack2(ai), vf = unpack2(af), vc = unpack2(ac);
            const int base = (b * 32 + lane) * 51 + wid;   // 51 coprime w/ 32: conflict-free
            red[base]      = vi.x + vi.y;
            red[base + 16] = vf.x + vf.y;
            red[base + 32] = vc.x + vc.y;
        }
        __syncthreads();

        // gate role: warps 0-7
        if (wid < 8) {
            float zi = xz0, zf = xz1, zc = xz2;
            const int rbase = (wid * 32 + lane) * 51;
#pragma unroll
            for (int kg = 0; kg < 16; kg++) {
                zi += red[rbase + kg];
                zf += red[rbase + 16 + kg];
                zc += red[rbase + 32 + kg];
            }
            const float ig = fast_sig(zi);
            const float fg = fast_sig(zf);
            c = fg * c + ig * fast_tanh(zc);
            const float o = fast_sig(s0 * aw0 + s1 * aw1 + s2 * aw2 + abr);
            const float h = o * fast_tanh(c);

            // pair h values across adjacent lanes (full-warp shfl, no divergence)
            const float hh = __shfl_down_sync(0xffffffffu, h, 1);
            if (t < T_ - 1 && !(lane & 1)) {
                const u64 hp2 = pack2(h, hh);
                const uint32_t hoff = p ? 0u : 8192u;   // target buffer hs[p^1]
                const uint32_t moff = p ? 0u : 8u;      // target mbar (mb0/mb1)
#pragma unroll
                for (int r = 0; r < 8; r++)
                    st_async_b64(rh0[r] + hoff, hp2, rm0[r] + moff);
            }
            yp[(size_t)t * U_] = h;

            if (t < T_ - 1) {   // prefetch next step's gate inputs under the wait
                const size_t o1 = (size_t)(t + 1) * NG;
                xz0 = __ldg(&xzp[o1]);
                xz1 = __ldg(&xzp[o1 + 256]);
                xz2 = __ldg(&xzp[o1 + 512]);
                s0 = __ldg(&so0[t + 1]); s1 = __ldg(&so1[t + 1]); s2 = __ldg(&so2[t + 1]);
            }
        }
    }
    asm volatile("barrier.cluster.arrive.aligned;\n\t"
                 "barrier.cluster.wait.aligned;" ::: "memory");
}

// ---------------------------------------------------------------- launch
extern "C" void kernel_launch(void* const* d_in, const int* in_sizes, int n_in,
                              void* d_out, int out_size) {
    const float* x    = (const float*)d_in[0];
    const float* ker  = (const float*)d_in[1];
    const float* rk   = (const float*)d_in[2];
    const float* bias = (const float*)d_in[3];
    const float* stk  = (const float*)d_in[4];
    const float* srk  = (const float*)d_in[5];
    const float* aw   = (const float*)d_in[6];
    const float* ab   = (const float*)d_in[7];
    const float* kbw  = (const float*)d_in[8];
    const float* ksw  = (const float*)d_in[9];
    float* out = (float*)d_out;

    k1_gemm<<<dim3(NG / 128, M_ / 128), 256>>>(x, ker, bias);
    k2_sub<<<3 * B_, 256>>>(x, stk, srk, kbw, ksw);
    k3_rnn<<<128, 512>>>(rk, aw, ab, out);
}